// round 1
// baseline (speedup 1.0000x reference)
#include <cuda_runtime.h>
#include <cstdint>

#define B_   1024
#define S_   128
#define E_   256
#define H_   8
#define D_   64
#define HD_  512

// Packed weight layout: [proj p<4][head h<8][chunk c<8][n<64][k'<40]
// k' pairing inside each 8-wide k-tile: k' = kt*8 + 2t   -> logical k = c*32 + kt*8 + t
//                                       k' = kt*8 + 2t+1 -> logical k = c*32 + kt*8 + t + 4
// so one LDS.64 yields the (b0,b1) fragment pair for mma.m16n8k8.
#define KP 40
#define NCHUNK 8
#define CHUNK_FLOATS (64 * KP)          // 2560 floats = 10240 B per chunk

__device__ __align__(16) float g_Wpk[4 * 8 * NCHUNK * CHUNK_FLOATS];

// smem layout (floats):
//  Xp : [128][264]  k-paired tf32 X        off 0      (33792)
//  Wc : 2 x CHUNK_FLOATS double buffer     off 33792  (5120)
//  Ks : [128][72]   K row-major            off 38912  (9216)
//  Vt : [64][136]   V transposed           off 48128  (8704)
#define SM_XP 0
#define SM_WC 33792
#define SM_KS 38912
#define SM_VT 48128
#define SM_FLOATS 56832                  // 227,328 bytes

__device__ __forceinline__ float f2tf(float x) {
    uint32_t u;
    asm("cvt.rna.tf32.f32 %0, %1;" : "=r"(u) : "f"(x));
    return __uint_as_float(u);
}

__device__ __forceinline__ void mma8(float c[4],
                                     uint32_t a0, uint32_t a1, uint32_t a2, uint32_t a3,
                                     uint32_t b0, uint32_t b1) {
    asm volatile(
        "mma.sync.aligned.m16n8k8.row.col.f32.tf32.tf32.f32 "
        "{%0,%1,%2,%3},{%4,%5,%6,%7},{%8,%9},{%0,%1,%2,%3};"
        : "+f"(c[0]), "+f"(c[1]), "+f"(c[2]), "+f"(c[3])
        : "r"(a0), "r"(a1), "r"(a2), "r"(a3), "r"(b0), "r"(b1));
}

__device__ __forceinline__ void cpa16(void* smem_dst, const void* gsrc) {
    uint32_t s = (uint32_t)__cvta_generic_to_shared(smem_dst);
    asm volatile("cp.async.cg.shared.global [%0], [%1], 16;" :: "r"(s), "l"(gsrc));
}

// ---------------------------------------------------------------------------
// Prep: re-round weights to tf32 (rna) and repack into fragment-native layout.
// Deterministic; rerun on every launch (tiny: 2.6 MB write).
// ---------------------------------------------------------------------------
__global__ void prep_kernel(const float* __restrict__ wq, const float* __restrict__ wk,
                            const float* __restrict__ wv, const float* __restrict__ wr) {
    const float* Ws[4] = {wq, wk, wv, wr};
    int total = 4 * 8 * NCHUNK * CHUNK_FLOATS;
    for (int idx = blockIdx.x * blockDim.x + threadIdx.x; idx < total;
         idx += gridDim.x * blockDim.x) {
        int kp = idx % KP;
        int rest = idx / KP;
        int n = rest % 64; rest /= 64;
        int c = rest % NCHUNK; rest /= NCHUNK;
        int h = rest % 8;
        int p = rest / 8;
        float v = 0.0f;
        if (kp < 32) {
            int kt = kp >> 3, q = kp & 7;
            int klog = c * 32 + kt * 8 + (q >> 1) + (q & 1) * 4;
            v = f2tf(Ws[p][klog * HD_ + h * 64 + n]);
        }
        g_Wpk[idx] = v;
    }
}

// ---------------------------------------------------------------------------
// One projection GEMM: acc[16 rows x 64 cols per warp] += Xp @ Wslice
// Double-buffered cp.async staging of pre-packed W chunks.
// ---------------------------------------------------------------------------
__device__ __forceinline__ void proj_gemm(const float* __restrict__ gWph, float* sm,
                                          int r0, int g, int t, float acc[8][4]) {
    float* Wc = sm + SM_WC;
    const float* Xp = sm + SM_XP;
    int tid = threadIdx.x;

#pragma unroll
    for (int j = 0; j < 8; ++j)
#pragma unroll
        for (int i = 0; i < 4; ++i) acc[j][i] = 0.0f;

    // prologue: chunk 0 -> buf 0
    for (int i = tid; i < CHUNK_FLOATS / 4; i += 256)
        cpa16(Wc + i * 4, gWph + i * 4);
    asm volatile("cp.async.commit_group;");

    for (int c = 0; c < NCHUNK; ++c) {
        if (c + 1 < NCHUNK) {
            float* dst = Wc + ((c + 1) & 1) * CHUNK_FLOATS;
            const float* src = gWph + (c + 1) * CHUNK_FLOATS;
            for (int i = tid; i < CHUNK_FLOATS / 4; i += 256)
                cpa16(dst + i * 4, src + i * 4);
            asm volatile("cp.async.commit_group;");
            asm volatile("cp.async.wait_group 1;");
        } else {
            asm volatile("cp.async.wait_group 0;");
        }
        __syncthreads();
        const float* Wb = Wc + (c & 1) * CHUNK_FLOATS;
#pragma unroll
        for (int kk = 0; kk < 4; ++kk) {
            int xcol = c * 32 + kk * 8 + 2 * t;
            float2 alo = *(const float2*)&Xp[(r0 + g) * 264 + xcol];
            float2 ahi = *(const float2*)&Xp[(r0 + g + 8) * 264 + xcol];
            uint32_t a0 = __float_as_uint(alo.x), a2 = __float_as_uint(alo.y);
            uint32_t a1 = __float_as_uint(ahi.x), a3 = __float_as_uint(ahi.y);
#pragma unroll
            for (int j = 0; j < 8; ++j) {
                float2 b = *(const float2*)&Wb[(j * 8 + g) * KP + kk * 8 + 2 * t];
                mma8(acc[j], a0, a1, a2, a3, __float_as_uint(b.x), __float_as_uint(b.y));
            }
        }
        __syncthreads();
    }
}

// ---------------------------------------------------------------------------
// Fused MHA: one CTA per batch, 8 warps x 16 rows.
// ---------------------------------------------------------------------------
__global__ void __launch_bounds__(256, 1)
mha_kernel(const float* __restrict__ X, float* __restrict__ Out) {
    extern __shared__ float sm[];
    int b = blockIdx.x, tid = threadIdx.x;
    int w = tid >> 5, lane = tid & 31, g = lane >> 2, t = lane & 3;
    int r0 = w * 16;

    const float* Xg = X + (size_t)b * (S_ * E_);

    // Stage X -> Xp with tf32 round + k-pairing (A-frag pairs adjacent).
    for (int i = tid; i < S_ * E_ / 4; i += 256) {
        int r = i >> 6;
        int c4 = (i & 63) * 4;
        float4 v = *(const float4*)&Xg[r * E_ + c4];
        float vv[4] = {v.x, v.y, v.z, v.w};
#pragma unroll
        for (int e = 0; e < 4; ++e) {
            int col = c4 + e;
            int kt = col >> 3, q = col & 7;
            int kp = kt * 8 + ((q < 4) ? 2 * q : 2 * (q - 4) + 1);
            sm[SM_XP + r * 264 + kp] = f2tf(vv[e]);
        }
    }
    __syncthreads();

    float* Ks = sm + SM_KS;
    float* Vt = sm + SM_VT;

    for (int h = 0; h < H_; ++h) {
        float accT[8][4], qf[8][4], rf[8][4];

        // ---- K projection -> smem row-major [s][d] ----
        proj_gemm(g_Wpk + (size_t)((1 * 8 + h) * NCHUNK) * CHUNK_FLOATS, sm, r0, g, t, accT);
#pragma unroll
        for (int j = 0; j < 8; ++j) {
            *(float2*)&Ks[(r0 + g) * 72 + j * 8 + 2 * t] =
                make_float2(f2tf(accT[j][0]), f2tf(accT[j][1]));
            *(float2*)&Ks[(r0 + g + 8) * 72 + j * 8 + 2 * t] =
                make_float2(f2tf(accT[j][2]), f2tf(accT[j][3]));
        }

        // ---- V projection -> smem transposed [d][s] ----
        proj_gemm(g_Wpk + (size_t)((2 * 8 + h) * NCHUNK) * CHUNK_FLOATS, sm, r0, g, t, accT);
#pragma unroll
        for (int j = 0; j < 8; ++j) {
            Vt[(j * 8 + 2 * t) * 136 + r0 + g]         = f2tf(accT[j][0]);
            Vt[(j * 8 + 2 * t + 1) * 136 + r0 + g]     = f2tf(accT[j][1]);
            Vt[(j * 8 + 2 * t) * 136 + r0 + g + 8]     = f2tf(accT[j][2]);
            Vt[(j * 8 + 2 * t + 1) * 136 + r0 + g + 8] = f2tf(accT[j][3]);
        }

        // ---- Q projection -> registers (tf32) ----
        proj_gemm(g_Wpk + (size_t)((0 * 8 + h) * NCHUNK) * CHUNK_FLOATS, sm, r0, g, t, qf);
#pragma unroll
        for (int j = 0; j < 8; ++j)
#pragma unroll
            for (int i = 0; i < 4; ++i) qf[j][i] = f2tf(qf[j][i]);

        // ---- residual projection -> registers (fp32) ----
        proj_gemm(g_Wpk + (size_t)((3 * 8 + h) * NCHUNK) * CHUNK_FLOATS, sm, r0, g, t, rf);

        __syncthreads();  // Ks/Vt fully written by all warps

        // ---- scores = Q @ K^T  (Q C-frags reused as A via k-order permutation) ----
        float s[16][4];
#pragma unroll
        for (int n = 0; n < 16; ++n)
#pragma unroll
            for (int i = 0; i < 4; ++i) s[n][i] = 0.0f;
#pragma unroll
        for (int jq = 0; jq < 8; ++jq) {
            uint32_t a0 = __float_as_uint(qf[jq][0]);
            uint32_t a1 = __float_as_uint(qf[jq][2]);
            uint32_t a2 = __float_as_uint(qf[jq][1]);
            uint32_t a3 = __float_as_uint(qf[jq][3]);
#pragma unroll
            for (int n = 0; n < 16; ++n) {
                float2 bb = *(const float2*)&Ks[(n * 8 + g) * 72 + jq * 8 + 2 * t];
                mma8(s[n], a0, a1, a2, a3, __float_as_uint(bb.x), __float_as_uint(bb.y));
            }
        }

        // ---- softmax over rows r0+g (regs 0,1) and r0+g+8 (regs 2,3) ----
        float m0 = -1e30f, m1 = -1e30f;
#pragma unroll
        for (int n = 0; n < 16; ++n) {
            m0 = fmaxf(m0, fmaxf(s[n][0], s[n][1]));
            m1 = fmaxf(m1, fmaxf(s[n][2], s[n][3]));
        }
        m0 = fmaxf(m0, __shfl_xor_sync(0xffffffffu, m0, 1));
        m0 = fmaxf(m0, __shfl_xor_sync(0xffffffffu, m0, 2));
        m1 = fmaxf(m1, __shfl_xor_sync(0xffffffffu, m1, 1));
        m1 = fmaxf(m1, __shfl_xor_sync(0xffffffffu, m1, 2));

        const float L2E = 1.4426950408889634f;
        float sum0 = 0.0f, sum1 = 0.0f;
#pragma unroll
        for (int n = 0; n < 16; ++n) {
            float p0 = exp2f((s[n][0] - m0) * L2E);
            float p1 = exp2f((s[n][1] - m0) * L2E);
            float p2 = exp2f((s[n][2] - m1) * L2E);
            float p3 = exp2f((s[n][3] - m1) * L2E);
            sum0 += p0 + p1;
            sum1 += p2 + p3;
            s[n][0] = f2tf(p0); s[n][1] = f2tf(p1);
            s[n][2] = f2tf(p2); s[n][3] = f2tf(p3);
        }
        sum0 += __shfl_xor_sync(0xffffffffu, sum0, 1);
        sum0 += __shfl_xor_sync(0xffffffffu, sum0, 2);
        sum1 += __shfl_xor_sync(0xffffffffu, sum1, 1);
        sum1 += __shfl_xor_sync(0xffffffffu, sum1, 2);
        float sc0 = 1.0f / sum0, sc1 = 1.0f / sum1;

        // ---- O = P @ V  (P C-frags reused as A; V read transposed) ----
        float o[8][4];
#pragma unroll
        for (int j = 0; j < 8; ++j)
#pragma unroll
            for (int i = 0; i < 4; ++i) o[j][i] = 0.0f;
#pragma unroll
        for (int js = 0; js < 16; ++js) {
            uint32_t a0 = __float_as_uint(s[js][0]);
            uint32_t a1 = __float_as_uint(s[js][2]);
            uint32_t a2 = __float_as_uint(s[js][1]);
            uint32_t a3 = __float_as_uint(s[js][3]);
#pragma unroll
            for (int j = 0; j < 8; ++j) {
                float2 bb = *(const float2*)&Vt[(j * 8 + g) * 136 + js * 8 + 2 * t];
                mma8(o[j], a0, a1, a2, a3, __float_as_uint(bb.x), __float_as_uint(bb.y));
            }
        }

        // ---- epilogue: out = relu(O/rowsum + R) ----
        size_t ob = (size_t)b * S_ * HD_ + (size_t)h * 64;
#pragma unroll
        for (int j = 0; j < 8; ++j) {
            float2 lo, hi;
            lo.x = fmaxf(o[j][0] * sc0 + rf[j][0], 0.0f);
            lo.y = fmaxf(o[j][1] * sc0 + rf[j][1], 0.0f);
            hi.x = fmaxf(o[j][2] * sc1 + rf[j][2], 0.0f);
            hi.y = fmaxf(o[j][3] * sc1 + rf[j][3], 0.0f);
            *(float2*)&Out[ob + (size_t)(r0 + g) * HD_ + j * 8 + 2 * t] = lo;
            *(float2*)&Out[ob + (size_t)(r0 + g + 8) * HD_ + j * 8 + 2 * t] = hi;
        }
        __syncthreads();  // protect Ks/Vt before next head overwrites
    }
}

extern "C" void kernel_launch(void* const* d_in, const int* in_sizes, int n_in,
                              void* d_out, int out_size) {
    const float* x  = (const float*)d_in[0];
    const float* wq = (const float*)d_in[1];
    const float* wk = (const float*)d_in[2];
    const float* wv = (const float*)d_in[3];
    const float* wr = (const float*)d_in[4];
    float* out = (float*)d_out;

    cudaFuncSetAttribute(mha_kernel, cudaFuncAttributeMaxDynamicSharedMemorySize,
                         SM_FLOATS * (int)sizeof(float));

    prep_kernel<<<2560, 256>>>(wq, wk, wv, wr);
    mha_kernel<<<B_, 256, SM_FLOATS * (int)sizeof(float)>>>(x, out);
}

// round 2
// speedup vs baseline: 1.0008x; 1.0008x over previous
#include <cuda_runtime.h>
#include <cstdint>

#define B_   1024
#define S_   128
#define E_   256
#define H_   8
#define D_   64
#define HD_  512

// Packed weight layout: [proj p<4][head h<8][chunk c<8][n<64][k'<40]
// k' pairing inside each 8-wide k-tile: k' = kt*8 + 2t   -> logical k = c*32 + kt*8 + t
//                                       k' = kt*8 + 2t+1 -> logical k = c*32 + kt*8 + t + 4
// so one LDS.64 yields the (b0,b1) fragment pair for mma.m16n8k8.
#define KP 40
#define NCHUNK 8
#define CHUNK_FLOATS (64 * KP)          // 2560 floats = 10240 B per chunk

__device__ __align__(16) float g_Wpk[4 * 8 * NCHUNK * CHUNK_FLOATS];

// smem layout (floats):
//  Xp : [128][264]  k-paired tf32 X        off 0      (33792)
//  Wc : 2 x CHUNK_FLOATS double buffer     off 33792  (5120)
//  Ks : [128][72]   K row-major            off 38912  (9216)
//  Vt : [64][136]   V transposed           off 48128  (8704)
#define SM_XP 0
#define SM_WC 33792
#define SM_KS 38912
#define SM_VT 48128
#define SM_FLOATS 56832                  // 227,328 bytes

__device__ __forceinline__ float f2tf(float x) {
    uint32_t u;
    asm("cvt.rna.tf32.f32 %0, %1;" : "=r"(u) : "f"(x));
    return __uint_as_float(u);
}

__device__ __forceinline__ void mma8(float c[4],
                                     uint32_t a0, uint32_t a1, uint32_t a2, uint32_t a3,
                                     uint32_t b0, uint32_t b1) {
    asm volatile(
        "mma.sync.aligned.m16n8k8.row.col.f32.tf32.tf32.f32 "
        "{%0,%1,%2,%3},{%4,%5,%6,%7},{%8,%9},{%0,%1,%2,%3};"
        : "+f"(c[0]), "+f"(c[1]), "+f"(c[2]), "+f"(c[3])
        : "r"(a0), "r"(a1), "r"(a2), "r"(a3), "r"(b0), "r"(b1));
}

__device__ __forceinline__ void cpa16(void* smem_dst, const void* gsrc) {
    uint32_t s = (uint32_t)__cvta_generic_to_shared(smem_dst);
    asm volatile("cp.async.cg.shared.global [%0], [%1], 16;" :: "r"(s), "l"(gsrc));
}

// ---------------------------------------------------------------------------
// Prep: re-round weights to tf32 (rna) and repack into fragment-native layout.
// Deterministic; rerun on every launch (tiny: 2.6 MB write).
// ---------------------------------------------------------------------------
__global__ void prep_kernel(const float* __restrict__ wq, const float* __restrict__ wk,
                            const float* __restrict__ wv, const float* __restrict__ wr) {
    const float* Ws[4] = {wq, wk, wv, wr};
    int total = 4 * 8 * NCHUNK * CHUNK_FLOATS;
    for (int idx = blockIdx.x * blockDim.x + threadIdx.x; idx < total;
         idx += gridDim.x * blockDim.x) {
        int kp = idx % KP;
        int rest = idx / KP;
        int n = rest % 64; rest /= 64;
        int c = rest % NCHUNK; rest /= NCHUNK;
        int h = rest % 8;
        int p = rest / 8;
        float v = 0.0f;
        if (kp < 32) {
            int kt = kp >> 3, q = kp & 7;
            int klog = c * 32 + kt * 8 + (q >> 1) + (q & 1) * 4;
            v = f2tf(Ws[p][klog * HD_ + h * 64 + n]);
        }
        g_Wpk[idx] = v;
    }
}

// ---------------------------------------------------------------------------
// One projection GEMM: acc[16 rows x 64 cols per warp] += Xp @ Wslice
// Double-buffered cp.async staging of pre-packed W chunks.
// ---------------------------------------------------------------------------
__device__ __forceinline__ void proj_gemm(const float* __restrict__ gWph, float* sm,
                                          int r0, int g, int t, float acc[8][4]) {
    float* Wc = sm + SM_WC;
    const float* Xp = sm + SM_XP;
    int tid = threadIdx.x;

#pragma unroll
    for (int j = 0; j < 8; ++j)
#pragma unroll
        for (int i = 0; i < 4; ++i) acc[j][i] = 0.0f;

    // prologue: chunk 0 -> buf 0
    for (int i = tid; i < CHUNK_FLOATS / 4; i += 256)
        cpa16(Wc + i * 4, gWph + i * 4);
    asm volatile("cp.async.commit_group;");

    for (int c = 0; c < NCHUNK; ++c) {
        if (c + 1 < NCHUNK) {
            float* dst = Wc + ((c + 1) & 1) * CHUNK_FLOATS;
            const float* src = gWph + (c + 1) * CHUNK_FLOATS;
            for (int i = tid; i < CHUNK_FLOATS / 4; i += 256)
                cpa16(dst + i * 4, src + i * 4);
            asm volatile("cp.async.commit_group;");
            asm volatile("cp.async.wait_group 1;");
        } else {
            asm volatile("cp.async.wait_group 0;");
        }
        __syncthreads();
        const float* Wb = Wc + (c & 1) * CHUNK_FLOATS;
#pragma unroll
        for (int kk = 0; kk < 4; ++kk) {
            int xcol = c * 32 + kk * 8 + 2 * t;
            float2 alo = *(const float2*)&Xp[(r0 + g) * 264 + xcol];
            float2 ahi = *(const float2*)&Xp[(r0 + g + 8) * 264 + xcol];
            uint32_t a0 = __float_as_uint(alo.x), a2 = __float_as_uint(alo.y);
            uint32_t a1 = __float_as_uint(ahi.x), a3 = __float_as_uint(ahi.y);
#pragma unroll
            for (int j = 0; j < 8; ++j) {
                float2 b = *(const float2*)&Wb[(j * 8 + g) * KP + kk * 8 + 2 * t];
                mma8(acc[j], a0, a1, a2, a3, __float_as_uint(b.x), __float_as_uint(b.y));
            }
        }
        __syncthreads();
    }
}

// ---------------------------------------------------------------------------
// Fused MHA: one CTA per batch, 8 warps x 16 rows.
// ---------------------------------------------------------------------------
__global__ void __launch_bounds__(256, 1)
mha_kernel(const float* __restrict__ X, float* __restrict__ Out) {
    extern __shared__ float sm[];
    int b = blockIdx.x, tid = threadIdx.x;
    int w = tid >> 5, lane = tid & 31, g = lane >> 2, t = lane & 3;
    int r0 = w * 16;

    const float* Xg = X + (size_t)b * (S_ * E_);

    // Stage X -> Xp with tf32 round + k-pairing (A-frag pairs adjacent).
    for (int i = tid; i < S_ * E_ / 4; i += 256) {
        int r = i >> 6;
        int c4 = (i & 63) * 4;
        float4 v = *(const float4*)&Xg[r * E_ + c4];
        float vv[4] = {v.x, v.y, v.z, v.w};
#pragma unroll
        for (int e = 0; e < 4; ++e) {
            int col = c4 + e;
            int kt = col >> 3, q = col & 7;
            int kp = kt * 8 + ((q < 4) ? 2 * q : 2 * (q - 4) + 1);
            sm[SM_XP + r * 264 + kp] = f2tf(vv[e]);
        }
    }
    __syncthreads();

    float* Ks = sm + SM_KS;
    float* Vt = sm + SM_VT;

    for (int h = 0; h < H_; ++h) {
        float accT[8][4], qf[8][4], rf[8][4];

        // ---- K projection -> smem row-major [s][d] ----
        proj_gemm(g_Wpk + (size_t)((1 * 8 + h) * NCHUNK) * CHUNK_FLOATS, sm, r0, g, t, accT);
#pragma unroll
        for (int j = 0; j < 8; ++j) {
            *(float2*)&Ks[(r0 + g) * 72 + j * 8 + 2 * t] =
                make_float2(f2tf(accT[j][0]), f2tf(accT[j][1]));
            *(float2*)&Ks[(r0 + g + 8) * 72 + j * 8 + 2 * t] =
                make_float2(f2tf(accT[j][2]), f2tf(accT[j][3]));
        }

        // ---- V projection -> smem transposed [d][s] ----
        proj_gemm(g_Wpk + (size_t)((2 * 8 + h) * NCHUNK) * CHUNK_FLOATS, sm, r0, g, t, accT);
#pragma unroll
        for (int j = 0; j < 8; ++j) {
            Vt[(j * 8 + 2 * t) * 136 + r0 + g]         = f2tf(accT[j][0]);
            Vt[(j * 8 + 2 * t + 1) * 136 + r0 + g]     = f2tf(accT[j][1]);
            Vt[(j * 8 + 2 * t) * 136 + r0 + g + 8]     = f2tf(accT[j][2]);
            Vt[(j * 8 + 2 * t + 1) * 136 + r0 + g + 8] = f2tf(accT[j][3]);
        }

        // ---- Q projection -> registers (tf32) ----
        proj_gemm(g_Wpk + (size_t)((0 * 8 + h) * NCHUNK) * CHUNK_FLOATS, sm, r0, g, t, qf);
#pragma unroll
        for (int j = 0; j < 8; ++j)
#pragma unroll
            for (int i = 0; i < 4; ++i) qf[j][i] = f2tf(qf[j][i]);

        // ---- residual projection -> registers (fp32) ----
        proj_gemm(g_Wpk + (size_t)((3 * 8 + h) * NCHUNK) * CHUNK_FLOATS, sm, r0, g, t, rf);

        __syncthreads();  // Ks/Vt fully written by all warps

        // ---- scores = Q @ K^T  (Q C-frags reused as A via k-order permutation) ----
        float s[16][4];
#pragma unroll
        for (int n = 0; n < 16; ++n)
#pragma unroll
            for (int i = 0; i < 4; ++i) s[n][i] = 0.0f;
#pragma unroll
        for (int jq = 0; jq < 8; ++jq) {
            uint32_t a0 = __float_as_uint(qf[jq][0]);
            uint32_t a1 = __float_as_uint(qf[jq][2]);
            uint32_t a2 = __float_as_uint(qf[jq][1]);
            uint32_t a3 = __float_as_uint(qf[jq][3]);
#pragma unroll
            for (int n = 0; n < 16; ++n) {
                float2 bb = *(const float2*)&Ks[(n * 8 + g) * 72 + jq * 8 + 2 * t];
                mma8(s[n], a0, a1, a2, a3, __float_as_uint(bb.x), __float_as_uint(bb.y));
            }
        }

        // ---- softmax over rows r0+g (regs 0,1) and r0+g+8 (regs 2,3) ----
        float m0 = -1e30f, m1 = -1e30f;
#pragma unroll
        for (int n = 0; n < 16; ++n) {
            m0 = fmaxf(m0, fmaxf(s[n][0], s[n][1]));
            m1 = fmaxf(m1, fmaxf(s[n][2], s[n][3]));
        }
        m0 = fmaxf(m0, __shfl_xor_sync(0xffffffffu, m0, 1));
        m0 = fmaxf(m0, __shfl_xor_sync(0xffffffffu, m0, 2));
        m1 = fmaxf(m1, __shfl_xor_sync(0xffffffffu, m1, 1));
        m1 = fmaxf(m1, __shfl_xor_sync(0xffffffffu, m1, 2));

        const float L2E = 1.4426950408889634f;
        float sum0 = 0.0f, sum1 = 0.0f;
#pragma unroll
        for (int n = 0; n < 16; ++n) {
            float p0 = exp2f((s[n][0] - m0) * L2E);
            float p1 = exp2f((s[n][1] - m0) * L2E);
            float p2 = exp2f((s[n][2] - m1) * L2E);
            float p3 = exp2f((s[n][3] - m1) * L2E);
            sum0 += p0 + p1;
            sum1 += p2 + p3;
            s[n][0] = f2tf(p0); s[n][1] = f2tf(p1);
            s[n][2] = f2tf(p2); s[n][3] = f2tf(p3);
        }
        sum0 += __shfl_xor_sync(0xffffffffu, sum0, 1);
        sum0 += __shfl_xor_sync(0xffffffffu, sum0, 2);
        sum1 += __shfl_xor_sync(0xffffffffu, sum1, 1);
        sum1 += __shfl_xor_sync(0xffffffffu, sum1, 2);
        float sc0 = 1.0f / sum0, sc1 = 1.0f / sum1;

        // ---- O = P @ V  (P C-frags reused as A; V read transposed) ----
        float o[8][4];
#pragma unroll
        for (int j = 0; j < 8; ++j)
#pragma unroll
            for (int i = 0; i < 4; ++i) o[j][i] = 0.0f;
#pragma unroll
        for (int js = 0; js < 16; ++js) {
            uint32_t a0 = __float_as_uint(s[js][0]);
            uint32_t a1 = __float_as_uint(s[js][2]);
            uint32_t a2 = __float_as_uint(s[js][1]);
            uint32_t a3 = __float_as_uint(s[js][3]);
#pragma unroll
            for (int j = 0; j < 8; ++j) {
                float2 bb = *(const float2*)&Vt[(j * 8 + g) * 136 + js * 8 + 2 * t];
                mma8(o[j], a0, a1, a2, a3, __float_as_uint(bb.x), __float_as_uint(bb.y));
            }
        }

        // ---- epilogue: out = relu(O/rowsum + R) ----
        size_t ob = (size_t)b * S_ * HD_ + (size_t)h * 64;
#pragma unroll
        for (int j = 0; j < 8; ++j) {
            float2 lo, hi;
            lo.x = fmaxf(o[j][0] * sc0 + rf[j][0], 0.0f);
            lo.y = fmaxf(o[j][1] * sc0 + rf[j][1], 0.0f);
            hi.x = fmaxf(o[j][2] * sc1 + rf[j][2], 0.0f);
            hi.y = fmaxf(o[j][3] * sc1 + rf[j][3], 0.0f);
            *(float2*)&Out[ob + (size_t)(r0 + g) * HD_ + j * 8 + 2 * t] = lo;
            *(float2*)&Out[ob + (size_t)(r0 + g + 8) * HD_ + j * 8 + 2 * t] = hi;
        }
        __syncthreads();  // protect Ks/Vt before next head overwrites
    }
}

extern "C" void kernel_launch(void* const* d_in, const int* in_sizes, int n_in,
                              void* d_out, int out_size) {
    const float* x  = (const float*)d_in[0];
    const float* wq = (const float*)d_in[1];
    const float* wk = (const float*)d_in[2];
    const float* wv = (const float*)d_in[3];
    const float* wr = (const float*)d_in[4];
    float* out = (float*)d_out;

    cudaFuncSetAttribute(mha_kernel, cudaFuncAttributeMaxDynamicSharedMemorySize,
                         SM_FLOATS * (int)sizeof(float));

    prep_kernel<<<2560, 256>>>(wq, wk, wv, wr);
    mha_kernel<<<B_, 256, SM_FLOATS * (int)sizeof(float)>>>(x, out);
}

// round 9
// speedup vs baseline: 1.1282x; 1.1273x over previous
#include <cuda_runtime.h>
#include <cstdint>

#define S_  128
#define E_  256
#define HD_ 512

// W stream: 256 superchunks x 3072 floats (12288 B each).
// Superchunk u = h*32+it: it<16 -> [K chunk16][V chunk16]; it>=16 -> [Q chunk16][R chunk16].
// Each slot: [n<64][kp<24]; kp<16: kk=kp>>3,q=kp&7 -> k = base16 + kk*8 + (q>>1) + (q&1)*4.
__device__ __align__(16) float g_W[256 * 3072];

#define SM_XP 0
#define SM_W  135168
#define SM_KS 159744
#define SM_VT 196608
#define SMEM_BYTES 231424

__device__ __forceinline__ float f2tf(float x) {
    uint32_t u; asm("cvt.rna.tf32.f32 %0, %1;" : "=r"(u) : "f"(x)); return __uint_as_float(u);
}
__device__ __forceinline__ uint32_t fau(float x) { return __float_as_uint(x); }

__device__ __forceinline__ void mma8(float c[4],
                                     uint32_t a0, uint32_t a1, uint32_t a2, uint32_t a3,
                                     uint32_t b0, uint32_t b1) {
    asm volatile(
        "mma.sync.aligned.m16n8k8.row.col.f32.tf32.tf32.f32 "
        "{%0,%1,%2,%3},{%4,%5,%6,%7},{%8,%9},{%0,%1,%2,%3};"
        : "+f"(c[0]), "+f"(c[1]), "+f"(c[2]), "+f"(c[3])
        : "r"(a0), "r"(a1), "r"(a2), "r"(a3), "r"(b0), "r"(b1));
}
__device__ __forceinline__ void cpa16(void* smem_dst, const void* gsrc) {
    uint32_t s = (uint32_t)__cvta_generic_to_shared(smem_dst);
    asm volatile("cp.async.cg.shared.global [%0], [%1], 16;" :: "r"(s), "l"(gsrc));
}

// ---------------------------------------------------------------------------
// Prep: round W to tf32 and pack the 256-superchunk stream.
// ---------------------------------------------------------------------------
__global__ void prep_kernel(const float* __restrict__ wq, const float* __restrict__ wk,
                            const float* __restrict__ wv, const float* __restrict__ wr) {
    const float* Ws[4] = {wq, wk, wv, wr};
    int idx = blockIdx.x * blockDim.x + threadIdx.x;
    if (idx >= 256 * 3072) return;
    int kp   = idx % 24;
    int n    = (idx / 24) & 63;
    int slot = (idx / (24 * 64)) & 1;
    int it   = (idx / (24 * 64 * 2)) & 31;
    int h    = idx / (24 * 64 * 2 * 32);
    float v = 0.0f;
    if (kp < 16) {
        int kk = kp >> 3, q = kp & 7;
        int k = (it & 15) * 16 + kk * 8 + (q >> 1) + (q & 1) * 4;
        int p = (it < 16) ? (slot ? 2 : 1) : (slot ? 3 : 0);
        v = f2tf(Ws[p][(size_t)k * HD_ + h * 64 + n]);
    }
    g_W[idx] = v;
}

// ---------------------------------------------------------------------------
// Fused MHA: one CTA per batch, 8 warps.
// ---------------------------------------------------------------------------
__global__ void __launch_bounds__(256, 1)
mha_kernel(const float* __restrict__ X, float* __restrict__ Out) {
    extern __shared__ float sm[];
    int b = blockIdx.x, tid = threadIdx.x;
    int w = tid >> 5, lane = tid & 31, g = lane >> 2, t = lane & 3;

    // Stage X -> Xp (tf32 round + k-pairing, stride 264) — identical to R1.
    const float* Xg = X + (size_t)b * S_ * E_;
    for (int i = tid; i < S_ * E_ / 4; i += 256) {
        int r = i >> 6, c4 = (i & 63) * 4;
        float4 v = *(const float4*)&Xg[r * E_ + c4];
        float vv[4] = {v.x, v.y, v.z, v.w};
#pragma unroll
        for (int e = 0; e < 4; ++e) {
            int col = c4 + e, kt = col >> 3, q = col & 7;
            int kp = kt * 8 + ((q < 4) ? 2 * q : 2 * (q - 4) + 1);
            sm[r * 264 + kp] = f2tf(vv[e]);
        }
    }

    float* Wc = sm + SM_W / 4;
    float* Ks = sm + SM_KS / 4;
    float* Vt = sm + SM_VT / 4;

    // prologue: prefetch superchunk 0 into buf 0
    {
        const char* src = (const char*)g_W;
#pragma unroll
        for (int rep = 0; rep < 3; ++rep)
            cpa16((char*)Wc + tid * 16 + rep * 4096, src + tid * 16 + rep * 4096);
        asm volatile("cp.async.commit_group;" ::: "memory");
    }

    const float L2E = 1.4426950408889634f;

    for (int h = 0; h < 8; ++h) {
        float qf[8][4], rf[8][4];
#pragma unroll
        for (int j = 0; j < 8; ++j)
#pragma unroll
            for (int i = 0; i < 4; ++i) { qf[j][i] = 0.0f; rf[j][i] = 0.0f; }

        // ================= Phase 1: K (warps 0-3) & V (warps 4-7), 32-row tiles =================
        {
            float kv[2][8][4];
#pragma unroll
            for (int mi = 0; mi < 2; ++mi)
#pragma unroll
                for (int j = 0; j < 8; ++j)
#pragma unroll
                    for (int i = 0; i < 4; ++i) kv[mi][j][i] = 0.0f;

            int r0 = (w & 3) * 32;
            for (int it = 0; it < 16; ++it) {
                int u = h * 32 + it;
                __syncthreads();
                {
                    const char* src = (const char*)g_W + (size_t)(u + 1) * 12288;
                    char* dst = (char*)Wc + ((u + 1) & 1) * 12288;
#pragma unroll
                    for (int rep = 0; rep < 3; ++rep)
                        cpa16(dst + tid * 16 + rep * 4096, src + tid * 16 + rep * 4096);
                    asm volatile("cp.async.commit_group;" ::: "memory");
                    asm volatile("cp.async.wait_group 1;" ::: "memory");
                }
                __syncthreads();
                const float* Wb = Wc + (u & 1) * 3072 + (w >= 4 ? 1536 : 0);
#pragma unroll
                for (int kk = 0; kk < 2; ++kk) {
                    int col = (it * 2 + kk) * 8 + 2 * t;
                    float2 aA = *(const float2*)&sm[(r0 + g) * 264 + col];
                    float2 aB = *(const float2*)&sm[(r0 + g + 8) * 264 + col];
                    float2 aC = *(const float2*)&sm[(r0 + g + 16) * 264 + col];
                    float2 aD = *(const float2*)&sm[(r0 + g + 24) * 264 + col];
#pragma unroll
                    for (int j = 0; j < 8; ++j) {
                        float2 bb = *(const float2*)&Wb[(j * 8 + g) * 24 + kk * 8 + 2 * t];
                        uint32_t b0 = fau(bb.x), b1 = fau(bb.y);
                        mma8(kv[0][j], fau(aA.x), fau(aB.x), fau(aA.y), fau(aB.y), b0, b1);
                        mma8(kv[1][j], fau(aC.x), fau(aD.x), fau(aC.y), fau(aD.y), b0, b1);
                    }
                }
            }
            if (w < 4) {
#pragma unroll
                for (int mi = 0; mi < 2; ++mi)
#pragma unroll
                    for (int j = 0; j < 8; ++j) {
                        *(float2*)&Ks[(r0 + 16 * mi + g) * 72 + j * 8 + 2 * t] =
                            make_float2(f2tf(kv[mi][j][0]), f2tf(kv[mi][j][1]));
                        *(float2*)&Ks[(r0 + 16 * mi + g + 8) * 72 + j * 8 + 2 * t] =
                            make_float2(f2tf(kv[mi][j][2]), f2tf(kv[mi][j][3]));
                    }
            } else {
#pragma unroll
                for (int mi = 0; mi < 2; ++mi)
#pragma unroll
                    for (int j = 0; j < 8; ++j) {
                        Vt[(j * 8 + 2 * t) * 136 + r0 + 16 * mi + g]         = f2tf(kv[mi][j][0]);
                        Vt[(j * 8 + 2 * t + 1) * 136 + r0 + 16 * mi + g]     = f2tf(kv[mi][j][1]);
                        Vt[(j * 8 + 2 * t) * 136 + r0 + 16 * mi + g + 8]     = f2tf(kv[mi][j][2]);
                        Vt[(j * 8 + 2 * t + 1) * 136 + r0 + 16 * mi + g + 8] = f2tf(kv[mi][j][3]);
                    }
            }
        }

        // ================= Phase 2: Q+R merged (all warps, 16-row tiles, n=128) =================
        int r0 = w * 16;
        for (int it = 16; it < 32; ++it) {
            int u = h * 32 + it;
            __syncthreads();
            if (u + 1 < 256) {
                const char* src = (const char*)g_W + (size_t)(u + 1) * 12288;
                char* dst = (char*)Wc + ((u + 1) & 1) * 12288;
#pragma unroll
                for (int rep = 0; rep < 3; ++rep)
                    cpa16(dst + tid * 16 + rep * 4096, src + tid * 16 + rep * 4096);
                asm volatile("cp.async.commit_group;" ::: "memory");
                asm volatile("cp.async.wait_group 1;" ::: "memory");
            } else {
                asm volatile("cp.async.wait_group 0;" ::: "memory");
            }
            __syncthreads();
            const float* Wb = Wc + (u & 1) * 3072;
#pragma unroll
            for (int kk = 0; kk < 2; ++kk) {
                int col = ((it - 16) * 2 + kk) * 8 + 2 * t;
                float2 alo = *(const float2*)&sm[(r0 + g) * 264 + col];
                float2 ahi = *(const float2*)&sm[(r0 + g + 8) * 264 + col];
                uint32_t a0 = fau(alo.x), a1 = fau(ahi.x), a2 = fau(alo.y), a3 = fau(ahi.y);
#pragma unroll
                for (int j = 0; j < 8; ++j) {
                    float2 bq = *(const float2*)&Wb[(j * 8 + g) * 24 + kk * 8 + 2 * t];
                    mma8(qf[j], a0, a1, a2, a3, fau(bq.x), fau(bq.y));
                    float2 br = *(const float2*)&Wb[1536 + (j * 8 + g) * 24 + kk * 8 + 2 * t];
                    mma8(rf[j], a0, a1, a2, a3, fau(br.x), fau(br.y));
                }
            }
        }

        // round Q to tf32
#pragma unroll
        for (int j = 0; j < 8; ++j)
#pragma unroll
            for (int i = 0; i < 4; ++i) qf[j][i] = f2tf(qf[j][i]);

        // ---- scores = Q @ K^T (Q C-frags reused as A via k-order permutation) ----
        float s[16][4];
#pragma unroll
        for (int n = 0; n < 16; ++n)
#pragma unroll
            for (int i = 0; i < 4; ++i) s[n][i] = 0.0f;
#pragma unroll
        for (int jq = 0; jq < 8; ++jq) {
            uint32_t a0 = fau(qf[jq][0]);
            uint32_t a1 = fau(qf[jq][2]);
            uint32_t a2 = fau(qf[jq][1]);
            uint32_t a3 = fau(qf[jq][3]);
#pragma unroll
            for (int n = 0; n < 16; ++n) {
                float2 bb = *(const float2*)&Ks[(n * 8 + g) * 72 + jq * 8 + 2 * t];
                mma8(s[n], a0, a1, a2, a3, fau(bb.x), fau(bb.y));
            }
        }

        // ---- softmax (rows r0+g / r0+g+8) ----
        float m0 = -1e30f, m1 = -1e30f;
#pragma unroll
        for (int n = 0; n < 16; ++n) {
            m0 = fmaxf(m0, fmaxf(s[n][0], s[n][1]));
            m1 = fmaxf(m1, fmaxf(s[n][2], s[n][3]));
        }
        m0 = fmaxf(m0, __shfl_xor_sync(0xffffffffu, m0, 1));
        m0 = fmaxf(m0, __shfl_xor_sync(0xffffffffu, m0, 2));
        m1 = fmaxf(m1, __shfl_xor_sync(0xffffffffu, m1, 1));
        m1 = fmaxf(m1, __shfl_xor_sync(0xffffffffu, m1, 2));

        float sum0 = 0.0f, sum1 = 0.0f;
#pragma unroll
        for (int n = 0; n < 16; ++n) {
            float p0 = exp2f((s[n][0] - m0) * L2E);
            float p1 = exp2f((s[n][1] - m0) * L2E);
            float p2 = exp2f((s[n][2] - m1) * L2E);
            float p3 = exp2f((s[n][3] - m1) * L2E);
            sum0 += p0 + p1;
            sum1 += p2 + p3;
            s[n][0] = f2tf(p0); s[n][1] = f2tf(p1);
            s[n][2] = f2tf(p2); s[n][3] = f2tf(p3);
        }
        sum0 += __shfl_xor_sync(0xffffffffu, sum0, 1);
        sum0 += __shfl_xor_sync(0xffffffffu, sum0, 2);
        sum1 += __shfl_xor_sync(0xffffffffu, sum1, 1);
        sum1 += __shfl_xor_sync(0xffffffffu, sum1, 2);
        float sc0 = 1.0f / sum0, sc1 = 1.0f / sum1;

        // ---- O = P @ V ----
        float o[8][4];
#pragma unroll
        for (int j = 0; j < 8; ++j)
#pragma unroll
            for (int i = 0; i < 4; ++i) o[j][i] = 0.0f;
#pragma unroll
        for (int js = 0; js < 16; ++js) {
            uint32_t a0 = fau(s[js][0]);
            uint32_t a1 = fau(s[js][2]);
            uint32_t a2 = fau(s[js][1]);
            uint32_t a3 = fau(s[js][3]);
#pragma unroll
            for (int j = 0; j < 8; ++j) {
                float2 bb = *(const float2*)&Vt[(j * 8 + g) * 136 + js * 8 + 2 * t];
                mma8(o[j], a0, a1, a2, a3, fau(bb.x), fau(bb.y));
            }
        }

        // ---- epilogue: relu(O/rowsum + R) ----
        size_t ob = (size_t)b * S_ * HD_ + (size_t)h * 64;
#pragma unroll
        for (int j = 0; j < 8; ++j) {
            float2 lo, hi;
            lo.x = fmaxf(o[j][0] * sc0 + rf[j][0], 0.0f);
            lo.y = fmaxf(o[j][1] * sc0 + rf[j][1], 0.0f);
            hi.x = fmaxf(o[j][2] * sc1 + rf[j][2], 0.0f);
            hi.y = fmaxf(o[j][3] * sc1 + rf[j][3], 0.0f);
            *(float2*)&Out[ob + (size_t)(r0 + g) * HD_ + j * 8 + 2 * t] = lo;
            *(float2*)&Out[ob + (size_t)(r0 + g + 8) * HD_ + j * 8 + 2 * t] = hi;
        }
    }
}

extern "C" void kernel_launch(void* const* d_in, const int* in_sizes, int n_in,
                              void* d_out, int out_size) {
    const float* x  = (const float*)d_in[0];
    const float* wq = (const float*)d_in[1];
    const float* wk = (const float*)d_in[2];
    const float* wv = (const float*)d_in[3];
    const float* wr = (const float*)d_in[4];
    float* out = (float*)d_out;

    cudaFuncSetAttribute(mha_kernel, cudaFuncAttributeMaxDynamicSharedMemorySize, SMEM_BYTES);
    prep_kernel<<<3072, 256>>>(wq, wk, wv, wr);
    mha_kernel<<<1024, 256, SMEM_BYTES>>>(x, out);
}